// round 3
// baseline (speedup 1.0000x reference)
#include <cuda_runtime.h>
#include <cstdint>

// SpatialDeformer3D: trilinear warp of X[...,0] by per-voxel deformation.
// Shapes fixed by the problem: B=2, H=160, W=192, D=160.
// X:           (B,H,W,D,2) float32   -- only channel 0 is sampled
// deformation: (B,H,W,D,3) float32   -- (dx in W, dy in H, dz in D)
// out:         (B,H,W,D,1) float32

namespace {
constexpr int B = 2;
constexpr int H = 160;
constexpr int W = 192;
constexpr int D = 160;
constexpr int WD = W * D;           // 30720
constexpr int N = H * W * D;        // 4,915,200 voxels per batch
constexpr int QUADS = (B * N) / 4;  // 4 voxels per thread along z
}

__device__ __forceinline__ float clampi_f(int v, int hi, int* out_i) {
    int c = v < 0 ? 0 : (v > hi ? hi : v);
    *out_i = c;
    return (float)c;
}

__global__ void __launch_bounds__(256)
deform3d_kernel(const float* __restrict__ X,
                const float* __restrict__ def,
                float* __restrict__ out) {
    int t = blockIdx.x * blockDim.x + threadIdx.x;
    if (t >= QUADS) return;

    int r4 = t * 4;                 // global voxel index of first of 4 (b*N + r)
    int b  = r4 / N;
    int r  = r4 - b * N;            // voxel index within batch, multiple of 4
    int iy = r / WD;
    int rem = r - iy * WD;
    int ix = rem / D;
    int iz = rem - ix * D;          // multiple of 4; iz..iz+3 stay inside row (D%4==0)

    // Deformation: 12 consecutive floats, 16B-aligned (r4 multiple of 4 -> offset %48==0... %16==0)
    const float4* dp = reinterpret_cast<const float4*>(def + (size_t)r4 * 3);
    float4 v0 = dp[0];
    float4 v1 = dp[1];
    float4 v2 = dp[2];
    float dv[12] = {v0.x, v0.y, v0.z, v0.w,
                    v1.x, v1.y, v1.z, v1.w,
                    v2.x, v2.y, v2.z, v2.w};

    const float* Xb = X + (size_t)b * N * 2;

    float res[4];
#pragma unroll
    for (int k = 0; k < 4; ++k) {
        float x = (float)ix       + dv[3 * k + 0];
        float y = (float)iy       + dv[3 * k + 1];
        float z = (float)(iz + k) + dv[3 * k + 2];

        int x0i = (int)floorf(x);
        int y0i = (int)floorf(y);
        int z0i = (int)floorf(z);

        int x0, x1, y0, y1, z0, z1;
        float x0f = clampi_f(x0i,     W - 1, &x0);
        float x1f = clampi_f(x0i + 1, W - 1, &x1);
        float y0f = clampi_f(y0i,     H - 1, &y0);
        float y1f = clampi_f(y0i + 1, H - 1, &y1);
        float z0f = clampi_f(z0i,     D - 1, &z0);
        float z1f = clampi_f(z0i + 1, D - 1, &z1);

        // Weights use CLAMPED coordinates (matches reference's post-clip x0f/x1f).
        float wx0 = x - x0f, wx1 = x1f - x;
        float wy0 = y - y0f, wy1 = y1f - y;
        float wz0 = z - z0f, wz1 = z1f - z;

        int oy0 = y0 * WD, oy1 = y1 * WD;
        int ox0 = x0 * D,  ox1 = x1 * D;

        // 8 gathers from channel 0 (stride-2 float layout)
        float p000 = __ldg(&Xb[(size_t)(oy0 + ox0 + z0) * 2]);
        float p001 = __ldg(&Xb[(size_t)(oy0 + ox0 + z1) * 2]);
        float p010 = __ldg(&Xb[(size_t)(oy0 + ox1 + z0) * 2]);
        float p011 = __ldg(&Xb[(size_t)(oy0 + ox1 + z1) * 2]);
        float p100 = __ldg(&Xb[(size_t)(oy1 + ox0 + z0) * 2]);
        float p101 = __ldg(&Xb[(size_t)(oy1 + ox0 + z1) * 2]);
        float p110 = __ldg(&Xb[(size_t)(oy1 + ox1 + z0) * 2]);
        float p111 = __ldg(&Xb[(size_t)(oy1 + ox1 + z1) * 2]);

        float c00 = wz1 * p000 + wz0 * p001;
        float c01 = wz1 * p010 + wz0 * p011;
        float c10 = wz1 * p100 + wz0 * p101;
        float c11 = wz1 * p110 + wz0 * p111;

        float c0 = wx1 * c00 + wx0 * c01;
        float c1 = wx1 * c10 + wx0 * c11;

        res[k] = wy1 * c0 + wy0 * c1;
    }

    float4 o;
    o.x = res[0]; o.y = res[1]; o.z = res[2]; o.w = res[3];
    reinterpret_cast<float4*>(out)[t] = o;
}

extern "C" void kernel_launch(void* const* d_in, const int* in_sizes, int n_in,
                              void* d_out, int out_size) {
    const float* X   = (const float*)d_in[0];
    const float* def = (const float*)d_in[1];
    float* out       = (float*)d_out;

    constexpr int threads = 256;
    constexpr int blocks  = (QUADS + threads - 1) / threads;  // 9600
    deform3d_kernel<<<blocks, threads>>>(X, def, out);
}

// round 4
// speedup vs baseline: 1.2604x; 1.2604x over previous
#include <cuda_runtime.h>
#include <cstdint>

// SpatialDeformer3D: trilinear warp of X[...,0] by per-voxel deformation.
// Shapes fixed: B=2, H=160, W=192, D=160.
// X:           (B,H,W,D,2) float32  -- only channel 0 sampled
// deformation: (B,H,W,D,3) float32
// out:         (B,H,W,D,1) float32
//
// R4 strategy (from ncu: L1tex 83%, L2 73%, DRAM 22.7% -> L1-wavefront-bound):
//  1. Pre-pass compacts X channel 0 into a __device__ scratch (39.3 MB, fits L2)
//     -> halves gather sector traffic, removes dead-channel overfetch.
//  2. Main kernel: ONE voxel per thread so warp lanes are z-contiguous
//     -> gather LDGs coalesce to ~1-2 lines/warp instead of 8.
//  3. Streaming hints on def/out so compacted X stays L2-resident.

namespace {
constexpr int B  = 2;
constexpr int H  = 160;
constexpr int W  = 192;
constexpr int D  = 160;
constexpr int WD = W * D;            // 30720
constexpr int N  = H * W * D;        // 4,915,200 per batch
constexpr int NT = B * N;            // 9,830,400 total voxels
}

// Compacted channel-0 volume (B*N floats = 39.3 MB). Static scratch (no allocs).
__device__ float g_xc[NT];

// ---------------------------------------------------------------------------
// Pre-pass: X (interleaved ch0,ch1) -> g_xc (ch0 only).
// Each thread: 2x float4 loads (4 voxels) -> 1x float4 store.
__global__ void __launch_bounds__(256)
compact_kernel(const float4* __restrict__ X4) {
    int i = blockIdx.x * blockDim.x + threadIdx.x;   // i in [0, NT/4)
    if (i >= NT / 4) return;
    float4 a = X4[2 * i];       // voxels 4i, 4i+1 (ch0,ch1,ch0,ch1)
    float4 b = X4[2 * i + 1];   // voxels 4i+2, 4i+3
    float4 o;
    o.x = a.x; o.y = a.z; o.z = b.x; o.w = b.z;
    reinterpret_cast<float4*>(g_xc)[i] = o;
}

// ---------------------------------------------------------------------------
__device__ __forceinline__ float clampi_f(int v, int hi, int* out_i) {
    int c = v < 0 ? 0 : (v > hi ? hi : v);
    *out_i = c;
    return (float)c;
}

__global__ void __launch_bounds__(256)
deform3d_kernel(const float* __restrict__ def,
                float* __restrict__ out) {
    int t = blockIdx.x * blockDim.x + threadIdx.x;
    if (t >= NT) return;

    int b   = t / N;
    int r   = t - b * N;
    int iy  = r / WD;
    int rem = r - iy * WD;
    int ix  = rem / D;
    int iz  = rem - ix * D;

    // Deformation: 3 consecutive floats; streaming (no reuse).
    const float* dp = def + (size_t)t * 3;
    float dx = __ldcs(dp + 0);
    float dy = __ldcs(dp + 1);
    float dz = __ldcs(dp + 2);

    float x = (float)ix + dx;
    float y = (float)iy + dy;
    float z = (float)iz + dz;

    int x0i = (int)floorf(x);
    int y0i = (int)floorf(y);
    int z0i = (int)floorf(z);

    int x0, x1, y0, y1, z0, z1;
    float x0f = clampi_f(x0i,     W - 1, &x0);
    float x1f = clampi_f(x0i + 1, W - 1, &x1);
    float y0f = clampi_f(y0i,     H - 1, &y0);
    float y1f = clampi_f(y0i + 1, H - 1, &y1);
    float z0f = clampi_f(z0i,     D - 1, &z0);
    float z1f = clampi_f(z0i + 1, D - 1, &z1);

    // Weights from CLAMPED coords (matches reference's post-clip semantics).
    float wx0 = x - x0f, wx1 = x1f - x;
    float wy0 = y - y0f, wy1 = y1f - y;
    float wz0 = z - z0f, wz1 = z1f - z;

    const float* Xb = g_xc + (size_t)b * N;
    int oy0 = y0 * WD, oy1 = y1 * WD;
    int ox0 = x0 * D,  ox1 = x1 * D;

    int i00 = oy0 + ox0;
    int i01 = oy0 + ox1;
    int i10 = oy1 + ox0;
    int i11 = oy1 + ox1;

    float p000 = __ldg(&Xb[i00 + z0]);
    float p001 = __ldg(&Xb[i00 + z1]);
    float p010 = __ldg(&Xb[i01 + z0]);
    float p011 = __ldg(&Xb[i01 + z1]);
    float p100 = __ldg(&Xb[i10 + z0]);
    float p101 = __ldg(&Xb[i10 + z1]);
    float p110 = __ldg(&Xb[i11 + z0]);
    float p111 = __ldg(&Xb[i11 + z1]);

    float c00 = wz1 * p000 + wz0 * p001;
    float c01 = wz1 * p010 + wz0 * p011;
    float c10 = wz1 * p100 + wz0 * p101;
    float c11 = wz1 * p110 + wz0 * p111;

    float c0 = wx1 * c00 + wx0 * c01;
    float c1 = wx1 * c10 + wx0 * c11;

    // Streaming store: don't let output evict L2-resident X.
    __stcs(out + t, wy1 * c0 + wy0 * c1);
}

extern "C" void kernel_launch(void* const* d_in, const int* in_sizes, int n_in,
                              void* d_out, int out_size) {
    const float* X   = (const float*)d_in[0];
    const float* def = (const float*)d_in[1];
    float* out       = (float*)d_out;

    constexpr int threads = 256;
    constexpr int pre_blocks  = (NT / 4 + threads - 1) / threads;  // 9600
    constexpr int main_blocks = (NT + threads - 1) / threads;      // 38400

    compact_kernel<<<pre_blocks, threads>>>(reinterpret_cast<const float4*>(X));
    deform3d_kernel<<<main_blocks, threads>>>(def, out);
}

// round 6
// speedup vs baseline: 1.2608x; 1.0003x over previous
#include <cuda_runtime.h>
#include <cstdint>

// SpatialDeformer3D: trilinear warp of X[...,0] by per-voxel deformation.
// Shapes fixed: B=2, H=160, W=192, D=160.
//
// R5 (from ncu: L1tex 78.4% is the binder; DRAM already near-minimal):
//  - keep channel-0 compaction pre-pass (X stays L2-resident)
//  - main kernel: 2 z-consecutive voxels per thread
//      * def  = 3x aligned LDG.64  (9 -> 3 wavefronts per 32 voxels)
//      * out  = 1x aligned float2 store
//      * gathers: z-pairs share cache lines (24 -> ~20 wf per 32 voxels)

namespace {
constexpr int B  = 2;
constexpr int H  = 160;
constexpr int W  = 192;
constexpr int D  = 160;
constexpr int WD = W * D;            // 30720
constexpr int N  = H * W * D;        // 4,915,200 per batch
constexpr int NT = B * N;            // 9,830,400 total voxels
}

// Compacted channel-0 volume (39.3 MB). Static scratch (no allocs allowed).
__device__ float g_xc[NT];

// ---------------------------------------------------------------------------
// Pre-pass: X interleaved (ch0,ch1) -> g_xc (ch0). 8 voxels per thread.
__global__ void __launch_bounds__(256)
compact_kernel(const float4* __restrict__ X4) {
    int i = blockIdx.x * blockDim.x + threadIdx.x;   // i in [0, NT/8)
    if (i >= NT / 8) return;
    float4 a = X4[4 * i + 0];
    float4 b = X4[4 * i + 1];
    float4 c = X4[4 * i + 2];
    float4 d = X4[4 * i + 3];
    float4 o0, o1;
    o0.x = a.x; o0.y = a.z; o0.z = b.x; o0.w = b.z;
    o1.x = c.x; o1.y = c.z; o1.z = d.x; o1.w = d.z;
    float4* dst = reinterpret_cast<float4*>(g_xc) + 2 * i;
    dst[0] = o0;
    dst[1] = o1;
}

// ---------------------------------------------------------------------------
__device__ __forceinline__ float clampi_f(int v, int hi, int* out_i) {
    int c = v < 0 ? 0 : (v > hi ? hi : v);
    *out_i = c;
    return (float)c;
}

__device__ __forceinline__ float sample_one(const float* __restrict__ Xb,
                                            int ix, int iy, int iz,
                                            float dx, float dy, float dz) {
    float x = (float)ix + dx;
    float y = (float)iy + dy;
    float z = (float)iz + dz;

    int x0i = (int)floorf(x);
    int y0i = (int)floorf(y);
    int z0i = (int)floorf(z);

    int x0, x1, y0, y1, z0, z1;
    float x0f = clampi_f(x0i,     W - 1, &x0);
    float x1f = clampi_f(x0i + 1, W - 1, &x1);
    float y0f = clampi_f(y0i,     H - 1, &y0);
    float y1f = clampi_f(y0i + 1, H - 1, &y1);
    float z0f = clampi_f(z0i,     D - 1, &z0);
    float z1f = clampi_f(z0i + 1, D - 1, &z1);

    // Weights from CLAMPED coords (reference clips before computing weights).
    float wx0 = x - x0f, wx1 = x1f - x;
    float wy0 = y - y0f, wy1 = y1f - y;
    float wz0 = z - z0f, wz1 = z1f - z;

    int oy0 = y0 * WD, oy1 = y1 * WD;
    int ox0 = x0 * D,  ox1 = x1 * D;
    int i00 = oy0 + ox0;
    int i01 = oy0 + ox1;
    int i10 = oy1 + ox0;
    int i11 = oy1 + ox1;

    float p000 = __ldg(&Xb[i00 + z0]);
    float p001 = __ldg(&Xb[i00 + z1]);
    float p010 = __ldg(&Xb[i01 + z0]);
    float p011 = __ldg(&Xb[i01 + z1]);
    float p100 = __ldg(&Xb[i10 + z0]);
    float p101 = __ldg(&Xb[i10 + z1]);
    float p110 = __ldg(&Xb[i11 + z0]);
    float p111 = __ldg(&Xb[i11 + z1]);

    float c00 = wz1 * p000 + wz0 * p001;
    float c01 = wz1 * p010 + wz0 * p011;
    float c10 = wz1 * p100 + wz0 * p101;
    float c11 = wz1 * p110 + wz0 * p111;

    float c0 = wx1 * c00 + wx0 * c01;
    float c1 = wx1 * c10 + wx0 * c11;

    return wy1 * c0 + wy0 * c1;
}

__global__ void __launch_bounds__(256)
deform3d_kernel(const float2* __restrict__ def2,   // def viewed as float2[]
                float2* __restrict__ out2) {
    int t = blockIdx.x * blockDim.x + threadIdx.x; // t in [0, NT/2)
    if (t >= NT / 2) return;

    int r2  = t * 2;              // first voxel (global)
    int b   = r2 / N;
    int r   = r2 - b * N;
    int iy  = r / WD;
    int rem = r - iy * WD;
    int ix  = rem / D;
    int iz  = rem - ix * D;       // even; iz+1 < D (D even)

    // 6 def floats for the voxel pair: three aligned 8-byte loads (streaming).
    float2 d0 = __ldcs(&def2[3 * t + 0]);   // (dxA, dyA)
    float2 d1 = __ldcs(&def2[3 * t + 1]);   // (dzA, dxB)
    float2 d2 = __ldcs(&def2[3 * t + 2]);   // (dyB, dzB)

    const float* Xb = g_xc + (size_t)b * N;

    float2 o;
    o.x = sample_one(Xb, ix, iy, iz,     d0.x, d0.y, d1.x);
    o.y = sample_one(Xb, ix, iy, iz + 1, d1.y, d2.x, d2.y);

    // Streaming store: keep compacted X resident in L2.
    __stcs(&out2[t], o);
}

extern "C" void kernel_launch(void* const* d_in, const int* in_sizes, int n_in,
                              void* d_out, int out_size) {
    const float* X   = (const float*)d_in[0];
    const float* def = (const float*)d_in[1];

    constexpr int threads = 256;
    constexpr int pre_blocks  = (NT / 8 + threads - 1) / threads;  // 4800
    constexpr int main_blocks = (NT / 2 + threads - 1) / threads;  // 19200

    compact_kernel<<<pre_blocks, threads>>>(reinterpret_cast<const float4*>(X));
    deform3d_kernel<<<main_blocks, threads>>>(
        reinterpret_cast<const float2*>(def),
        reinterpret_cast<float2*>(d_out));
}